// round 4
// baseline (speedup 1.0000x reference)
#include <cuda_runtime.h>
#include <cuda_bf16.h>
#include <cstdint>

#define N_NODES 50000
#define N_EDGES 800000
#define IN_CH   256
#define HEADS   8
#define HEAD_DIM 32
#define OUT_CH  256   // HEADS*HEAD_DIM
#define NEG_SLOPE 0.2f
#define LN_EPS 1e-5f
#define SOFTMAX_EPS 1e-16f

// ---------------- scratch (static device globals; no allocation) ----------------
__device__ float g_xp[N_NODES * OUT_CH];     // 51.2 MB
__device__ float g_ai[N_NODES * HEADS];
__device__ float g_aj[N_NODES * HEADS];
__device__ float g_ex[N_EDGES * HEADS];      // 25.6 MB
__device__ float g_denom[N_NODES * HEADS];
__device__ int   g_src[N_EDGES];
__device__ int   g_dst[N_EDGES];
__device__ int   g_count[N_NODES];
__device__ int   g_rowptr[N_NODES];
__device__ int   g_cursor[N_NODES];
__device__ int   g_csr[N_EDGES];
__device__ int   g_bsums[64];
__device__ int   g_is64;

// ---------------- dtype detect: int64 vs int32 edge_index ----------------
// int64 little-endian with values < 2^31: every odd int32 word is 0.
__global__ void k_detect(const int* __restrict__ ei32) {
    if (threadIdx.x == 0 && blockIdx.x == 0) {
        int is64 = 1;
        for (int i = 0; i < 128; i++) {
            if (ei32[2 * i + 1] != 0) { is64 = 0; break; }
        }
        g_is64 = is64;
    }
}

// ---------------- init: zero counters & denominators ----------------
__global__ void k_init() {
    int i = blockIdx.x * blockDim.x + threadIdx.x;
    if (i < N_NODES * HEADS) g_denom[i] = 0.0f;
    if (i < N_NODES)         g_count[i] = 0;
}

// ---------------- edge prep: (int64|int32) -> int32 + dst histogram ----------------
__global__ void k_prep(const void* __restrict__ ei) {
    int e = blockIdx.x * blockDim.x + threadIdx.x;
    if (e >= N_EDGES) return;
    int s, d;
    if (g_is64) {
        const long long* p = (const long long*)ei;
        s = (int)p[e];
        d = (int)p[N_EDGES + e];
    } else {
        const int* p = (const int*)ei;
        s = p[e];
        d = p[N_EDGES + e];
    }
    g_src[e] = s;
    g_dst[e] = d;
    atomicAdd(&g_count[d], 1);
}

// ---------------- SGEMM: xp = x @ W  (M=50000, N=256, K=256) ----------------
#define BM 128
#define BN 128
#define BK 8
#define TM 8
#define TN 8
__global__ __launch_bounds__(256) void k_gemm(const float* __restrict__ x,
                                              const float* __restrict__ w) {
    __shared__ float As[BK][BM];
    __shared__ float Bs[BK][BN + 4];
    int bn = blockIdx.x * BN;
    int bm = blockIdx.y * BM;
    int tid = threadIdx.x;

    int arow = tid >> 1;            // 0..127
    int acol = (tid & 1) * 4;       // 0 or 4
    int brow = tid >> 5;            // 0..7
    int bcol = (tid & 31) * 4;      // 0..124

    int tx = tid & 15, ty = tid >> 4;
    float acc[TM][TN];
#pragma unroll
    for (int i = 0; i < TM; i++)
#pragma unroll
        for (int j = 0; j < TN; j++) acc[i][j] = 0.0f;

    for (int k0 = 0; k0 < IN_CH; k0 += BK) {
        float4 av = make_float4(0.f, 0.f, 0.f, 0.f);
        int gr = bm + arow;
        if (gr < N_NODES)
            av = *(const float4*)(x + (size_t)gr * IN_CH + k0 + acol);
        As[acol + 0][arow] = av.x;
        As[acol + 1][arow] = av.y;
        As[acol + 2][arow] = av.z;
        As[acol + 3][arow] = av.w;

        float4 bv = *(const float4*)(w + (size_t)(k0 + brow) * OUT_CH + bn + bcol);
        Bs[brow][bcol + 0] = bv.x;
        Bs[brow][bcol + 1] = bv.y;
        Bs[brow][bcol + 2] = bv.z;
        Bs[brow][bcol + 3] = bv.w;
        __syncthreads();

#pragma unroll
        for (int kk = 0; kk < BK; kk++) {
            float a[TM], b[TN];
#pragma unroll
            for (int i = 0; i < TM; i += 4) {
                float4 v = *(const float4*)(&As[kk][ty * TM + i]);
                a[i] = v.x; a[i + 1] = v.y; a[i + 2] = v.z; a[i + 3] = v.w;
            }
#pragma unroll
            for (int j = 0; j < TN; j += 4) {
                float4 v = *(const float4*)(&Bs[kk][tx * TN + j]);
                b[j] = v.x; b[j + 1] = v.y; b[j + 2] = v.z; b[j + 3] = v.w;
            }
#pragma unroll
            for (int i = 0; i < TM; i++)
#pragma unroll
                for (int j = 0; j < TN; j++) acc[i][j] += a[i] * b[j];
        }
        __syncthreads();
    }

#pragma unroll
    for (int i = 0; i < TM; i++) {
        int gr = bm + ty * TM + i;
        if (gr < N_NODES) {
#pragma unroll
            for (int j = 0; j < TN; j += 4) {
                float4 v = make_float4(acc[i][j], acc[i][j + 1], acc[i][j + 2], acc[i][j + 3]);
                *(float4*)(g_xp + (size_t)gr * OUT_CH + bn + tx * TN + j) = v;
            }
        }
    }
}

// ---------------- per-node attention logits a_i, a_j ----------------
__global__ void k_att(const float* __restrict__ att) {
    int n = blockIdx.x;
    int h = threadIdx.x >> 5;
    int l = threadIdx.x & 31;
    float v = g_xp[(size_t)n * OUT_CH + h * HEAD_DIM + l];
    float pi = v * att[h * 2 * HEAD_DIM + l];
    float pj = v * att[h * 2 * HEAD_DIM + HEAD_DIM + l];
#pragma unroll
    for (int o = 16; o; o >>= 1) {
        pi += __shfl_down_sync(0xffffffffu, pi, o);
        pj += __shfl_down_sync(0xffffffffu, pj, o);
    }
    if (l == 0) {
        g_ai[n * HEADS + h] = pi;
        g_aj[n * HEADS + h] = pj;
    }
}

// ---------------- edge softmax numerators + denominator sums ----------------
// softmax is shift invariant; no max-subtraction needed (|alpha| small)
__global__ void k_softmax(void) {
    int tid = blockIdx.x * blockDim.x + threadIdx.x;  // e*8 + h
    if (tid >= N_EDGES * HEADS) return;
    int e = tid >> 3;
    int h = tid & 7;
    int d = g_dst[e];
    int s = g_src[e];
    float al = g_ai[d * HEADS + h] + g_aj[s * HEADS + h];
    al = (al >= 0.0f) ? al : NEG_SLOPE * al;
    float ex = __expf(al);
    g_ex[tid] = ex;
    atomicAdd(&g_denom[d * HEADS + h], ex);
}

// ---------------- scan (3 stages) -> rowptr, cursor ----------------
__global__ void k_scan1() {
    __shared__ int sh[1024];
    int i = blockIdx.x * 1024 + threadIdx.x;
    int v = (i < N_NODES) ? g_count[i] : 0;
    sh[threadIdx.x] = v;
    __syncthreads();
    for (int o = 1; o < 1024; o <<= 1) {
        int t = (threadIdx.x >= o) ? sh[threadIdx.x - o] : 0;
        __syncthreads();
        sh[threadIdx.x] += t;
        __syncthreads();
    }
    if (i < N_NODES) g_rowptr[i] = sh[threadIdx.x] - v;  // exclusive
    if (threadIdx.x == 1023) g_bsums[blockIdx.x] = sh[1023];
}

__global__ void k_scan2(int nb) {
    if (threadIdx.x == 0 && blockIdx.x == 0) {
        int acc = 0;
        for (int b = 0; b < nb; b++) {
            int t = g_bsums[b];
            g_bsums[b] = acc;
            acc += t;
        }
    }
}

__global__ void k_scan3() {
    int i = blockIdx.x * blockDim.x + threadIdx.x;
    if (i >= N_NODES) return;
    int r = g_rowptr[i] + g_bsums[i >> 10];
    g_rowptr[i] = r;
    g_cursor[i] = r;
}

// ---------------- scatter edge ids into CSR buckets ----------------
__global__ void k_scatter() {
    int e = blockIdx.x * blockDim.x + threadIdx.x;
    if (e >= N_EDGES) return;
    int p = atomicAdd(&g_cursor[g_dst[e]], 1);
    g_csr[p] = e;
}

// ---------------- aggregation + layernorm + elu + residual ----------------
#define AGG_CH 64
__global__ __launch_bounds__(256) void k_agg(const float* __restrict__ x,
                                             const float* __restrict__ ln_w,
                                             const float* __restrict__ ln_b,
                                             float* __restrict__ out) {
    int n = blockIdx.x;
    int c = threadIdx.x;       // channel 0..255
    int h = c >> 5;            // head

    __shared__ int   s_eidx[AGG_CH];
    __shared__ int   s_srcc[AGG_CH];
    __shared__ float s_w[AGG_CH][HEADS];
    __shared__ float red[8];

    int start = g_rowptr[n];
    int deg   = g_count[n];
    float invd = 1.0f / (g_denom[n * HEADS + h] + SOFTMAX_EPS);

    float acc = 0.0f;
    for (int base = 0; base < deg; base += AGG_CH) {
        int m = deg - base;
        if (m > AGG_CH) m = AGG_CH;
        __syncthreads();
        if (c < m) {
            int e = g_csr[start + base + c];
            s_eidx[c] = e;
            s_srcc[c] = g_src[e];
        }
        __syncthreads();
        for (int t = c; t < m * HEADS; t += 256)
            s_w[t >> 3][t & 7] = g_ex[s_eidx[t >> 3] * HEADS + (t & 7)];
        __syncthreads();
#pragma unroll 4
        for (int j = 0; j < m; j++)
            acc += g_xp[(size_t)s_srcc[j] * OUT_CH + c] * s_w[j][h];
    }
    acc *= invd;

    // ---- block reduce: mean ----
    float v = acc;
#pragma unroll
    for (int o = 16; o; o >>= 1) v += __shfl_down_sync(0xffffffffu, v, o);
    __syncthreads();
    if ((c & 31) == 0) red[c >> 5] = v;
    __syncthreads();
    if (c < 8) {
        float t = red[c];
#pragma unroll
        for (int o = 4; o; o >>= 1) t += __shfl_down_sync(0xffu, t, o);
        if (c == 0) red[0] = t;
    }
    __syncthreads();
    float mu = red[0] * (1.0f / OUT_CH);
    __syncthreads();

    // ---- block reduce: variance (two-pass for stability) ----
    float d0 = acc - mu;
    v = d0 * d0;
#pragma unroll
    for (int o = 16; o; o >>= 1) v += __shfl_down_sync(0xffffffffu, v, o);
    if ((c & 31) == 0) red[c >> 5] = v;
    __syncthreads();
    if (c < 8) {
        float t = red[c];
#pragma unroll
        for (int o = 4; o; o >>= 1) t += __shfl_down_sync(0xffu, t, o);
        if (c == 0) red[0] = t;
    }
    __syncthreads();
    float var = red[0] * (1.0f / OUT_CH);

    float val = d0 * rsqrtf(var + LN_EPS) * ln_w[c] + ln_b[c];
    val = (val > 0.0f) ? val : expm1f(val);
    out[(size_t)n * OUT_CH + c] = val + x[(size_t)n * OUT_CH + c];
}

// ---------------- launch ----------------
extern "C" void kernel_launch(void* const* d_in, const int* in_sizes, int n_in,
                              void* d_out, int out_size) {
    const float* x    = (const float*)d_in[0];
    const void*  ei   = d_in[1];
    const float* linw = (const float*)d_in[2];
    const float* att  = (const float*)d_in[3];
    const float* lnw  = (const float*)d_in[4];
    const float* lnb  = (const float*)d_in[5];
    float*       out  = (float*)d_out;

    (void)in_sizes; (void)n_in; (void)out_size;

    k_detect<<<1, 32>>>((const int*)ei);
    k_init<<<(N_NODES * HEADS + 255) / 256, 256>>>();
    k_prep<<<(N_EDGES + 255) / 256, 256>>>(ei);

    dim3 ggrid(OUT_CH / BN, (N_NODES + BM - 1) / BM);
    k_gemm<<<ggrid, 256>>>(x, linw);

    k_att<<<N_NODES, 256>>>(att);
    k_softmax<<<(N_EDGES * HEADS + 255) / 256, 256>>>();

    int nscan = (N_NODES + 1023) / 1024;   // 49
    k_scan1<<<nscan, 1024>>>();
    k_scan2<<<1, 32>>>(nscan);
    k_scan3<<<(N_NODES + 255) / 256, 256>>>();

    k_scatter<<<(N_EDGES + 255) / 256, 256>>>();

    k_agg<<<N_NODES, 256>>>(x, lnw, lnb, out);
}

// round 7
// speedup vs baseline: 1.2224x; 1.2224x over previous
#include <cuda_runtime.h>
#include <cuda_bf16.h>
#include <cstdint>

#define N_NODES 50000
#define N_EDGES 800000
#define IN_CH   256
#define HEADS   8
#define HEAD_DIM 32
#define OUT_CH  256   // HEADS*HEAD_DIM
#define NEG_SLOPE 0.2f
#define LN_EPS 1e-5f
#define SOFTMAX_EPS 1e-16f

// ---------------- scratch (static device globals; no allocation) ----------------
__device__ float g_xp[N_NODES * OUT_CH];     // 51.2 MB
__device__ float g_ai[N_NODES * HEADS];
__device__ float g_aj[N_NODES * HEADS];
__device__ float g_ex[N_EDGES * HEADS];      // 25.6 MB
__device__ float g_denom[N_NODES * HEADS];
__device__ int   g_src[N_EDGES];
__device__ int   g_dst[N_EDGES];
__device__ int   g_count[N_NODES];
__device__ int   g_rowptr[N_NODES];
__device__ int   g_cursor[N_NODES];
__device__ int   g_csr[N_EDGES];
__device__ int   g_bsums[64];
__device__ int   g_is64;

// ---------------- dtype detect: int64 vs int32 edge_index ----------------
__global__ void k_detect(const int* __restrict__ ei32) {
    if (threadIdx.x == 0 && blockIdx.x == 0) {
        int is64 = 1;
        for (int i = 0; i < 128; i++) {
            if (ei32[2 * i + 1] != 0) { is64 = 0; break; }
        }
        g_is64 = is64;
    }
}

// ---------------- init ----------------
__global__ void k_init() {
    int i = blockIdx.x * blockDim.x + threadIdx.x;
    if (i < N_NODES * HEADS) g_denom[i] = 0.0f;
    if (i < N_NODES)         g_count[i] = 0;
}

// ---------------- edge prep ----------------
__global__ void k_prep(const void* __restrict__ ei) {
    int e = blockIdx.x * blockDim.x + threadIdx.x;
    if (e >= N_EDGES) return;
    int s, d;
    if (g_is64) {
        const long long* p = (const long long*)ei;
        s = (int)p[e];
        d = (int)p[N_EDGES + e];
    } else {
        const int* p = (const int*)ei;
        s = p[e];
        d = p[N_EDGES + e];
    }
    g_src[e] = s;
    g_dst[e] = d;
    atomicAdd(&g_count[d], 1);
}

// ---------------- tf32 tensor-core GEMM: xp = x @ W ----------------
__device__ __forceinline__ uint32_t f2tf32(float f) {
    uint32_t u;
    asm("cvt.rna.tf32.f32 %0, %1;" : "=r"(u) : "f"(f));
    return u;
}

__device__ __forceinline__ void mma_tf32(float* c,
                                         uint32_t a0, uint32_t a1, uint32_t a2, uint32_t a3,
                                         uint32_t b0, uint32_t b1) {
    asm volatile(
        "mma.sync.aligned.m16n8k8.row.col.f32.tf32.tf32.f32 "
        "{%0,%1,%2,%3},{%4,%5,%6,%7},{%8,%9},{%0,%1,%2,%3};"
        : "+f"(c[0]), "+f"(c[1]), "+f"(c[2]), "+f"(c[3])
        : "r"(a0), "r"(a1), "r"(a2), "r"(a3), "r"(b0), "r"(b1));
}

#define GBM 128
#define GBN 128
#define GBK 32

__global__ __launch_bounds__(256) void k_gemm_tc(const float* __restrict__ x,
                                                 const float* __restrict__ w) {
    __shared__ uint32_t As[GBM][GBK + 4];   // 18.4 KB, bank-conflict-free frag loads
    __shared__ uint32_t Bs[GBK][GBN + 4];   // 16.9 KB

    int tid = threadIdx.x;
    int lane = tid & 31, wid = tid >> 5;
    int warp_m = wid >> 2;     // 0..1   -> 64 rows
    int warp_n = wid & 3;      // 0..3   -> 32 cols
    int bm = blockIdx.y * GBM;
    int bn = blockIdx.x * GBN;

    float acc[4][4][4];
#pragma unroll
    for (int i = 0; i < 4; i++)
#pragma unroll
        for (int j = 0; j < 4; j++)
#pragma unroll
            for (int k = 0; k < 4; k++) acc[i][j][k] = 0.0f;

    int lq = lane >> 2;   // 0..7
    int lr = lane & 3;    // 0..3

    for (int k0 = 0; k0 < IN_CH; k0 += GBK) {
        // load A tile 128x32 (1024 float4 / 256 thr = 4 each)
#pragma unroll
        for (int v = 0; v < 4; v++) {
            int idx = tid + v * 256;
            int row = idx >> 3;
            int col = (idx & 7) * 4;
            float4 a = make_float4(0.f, 0.f, 0.f, 0.f);
            if (bm + row < N_NODES)
                a = *(const float4*)(x + (size_t)(bm + row) * IN_CH + k0 + col);
            As[row][col + 0] = f2tf32(a.x);
            As[row][col + 1] = f2tf32(a.y);
            As[row][col + 2] = f2tf32(a.z);
            As[row][col + 3] = f2tf32(a.w);
        }
        // load B tile 32x128
#pragma unroll
        for (int v = 0; v < 4; v++) {
            int idx = tid + v * 256;
            int row = idx >> 5;
            int col = (idx & 31) * 4;
            float4 b = *(const float4*)(w + (size_t)(k0 + row) * OUT_CH + bn + col);
            Bs[row][col + 0] = f2tf32(b.x);
            Bs[row][col + 1] = f2tf32(b.y);
            Bs[row][col + 2] = f2tf32(b.z);
            Bs[row][col + 3] = f2tf32(b.w);
        }
        __syncthreads();

#pragma unroll
        for (int kk = 0; kk < 4; kk++) {
            uint32_t a[4][4], b[4][2];
            int kb = kk * 8;
#pragma unroll
            for (int mf = 0; mf < 4; mf++) {
                int ar = warp_m * 64 + mf * 16 + lq;
                a[mf][0] = As[ar][kb + lr];
                a[mf][1] = As[ar + 8][kb + lr];
                a[mf][2] = As[ar][kb + lr + 4];
                a[mf][3] = As[ar + 8][kb + lr + 4];
            }
#pragma unroll
            for (int nf = 0; nf < 4; nf++) {
                int bc = warp_n * 32 + nf * 8 + lq;
                b[nf][0] = Bs[kb + lr][bc];
                b[nf][1] = Bs[kb + lr + 4][bc];
            }
#pragma unroll
            for (int mf = 0; mf < 4; mf++)
#pragma unroll
                for (int nf = 0; nf < 4; nf++)
                    mma_tf32(acc[mf][nf], a[mf][0], a[mf][1], a[mf][2], a[mf][3],
                             b[nf][0], b[nf][1]);
        }
        __syncthreads();
    }

    // epilogue
#pragma unroll
    for (int mf = 0; mf < 4; mf++) {
        int r0 = bm + warp_m * 64 + mf * 16 + lq;
        int r1 = r0 + 8;
#pragma unroll
        for (int nf = 0; nf < 4; nf++) {
            int col = bn + warp_n * 32 + nf * 8 + 2 * lr;
            if (r0 < N_NODES)
                *(float2*)(g_xp + (size_t)r0 * OUT_CH + col) =
                    make_float2(acc[mf][nf][0], acc[mf][nf][1]);
            if (r1 < N_NODES)
                *(float2*)(g_xp + (size_t)r1 * OUT_CH + col) =
                    make_float2(acc[mf][nf][2], acc[mf][nf][3]);
        }
    }
}

// ---------------- per-node attention logits a_i, a_j ----------------
__global__ void k_att(const float* __restrict__ att) {
    int n = blockIdx.x;
    int h = threadIdx.x >> 5;
    int l = threadIdx.x & 31;
    float v = g_xp[(size_t)n * OUT_CH + h * HEAD_DIM + l];
    float pi = v * att[h * 2 * HEAD_DIM + l];
    float pj = v * att[h * 2 * HEAD_DIM + HEAD_DIM + l];
#pragma unroll
    for (int o = 16; o; o >>= 1) {
        pi += __shfl_down_sync(0xffffffffu, pi, o);
        pj += __shfl_down_sync(0xffffffffu, pj, o);
    }
    if (l == 0) {
        g_ai[n * HEADS + h] = pi;
        g_aj[n * HEADS + h] = pj;
    }
}

// ---------------- edge softmax: one thread per edge (8 heads) ----------------
// softmax is shift invariant; no max-subtraction needed (|alpha| small)
__global__ void k_softmax(void) {
    int e = blockIdx.x * blockDim.x + threadIdx.x;
    if (e >= N_EDGES) return;
    int d = g_dst[e];
    int s = g_src[e];
    float4 i0 = *(const float4*)(g_ai + d * HEADS);
    float4 i1 = *(const float4*)(g_ai + d * HEADS + 4);
    float4 j0 = *(const float4*)(g_aj + s * HEADS);
    float4 j1 = *(const float4*)(g_aj + s * HEADS + 4);
    float al[8] = {i0.x + j0.x, i0.y + j0.y, i0.z + j0.z, i0.w + j0.w,
                   i1.x + j1.x, i1.y + j1.y, i1.z + j1.z, i1.w + j1.w};
    float ex[8];
#pragma unroll
    for (int h = 0; h < 8; h++) {
        float a = al[h];
        a = (a >= 0.0f) ? a : NEG_SLOPE * a;
        ex[h] = __expf(a);
    }
    *(float4*)(g_ex + (size_t)e * HEADS)     = make_float4(ex[0], ex[1], ex[2], ex[3]);
    *(float4*)(g_ex + (size_t)e * HEADS + 4) = make_float4(ex[4], ex[5], ex[6], ex[7]);
#pragma unroll
    for (int h = 0; h < 8; h++)
        atomicAdd(&g_denom[d * HEADS + h], ex[h]);
}

// ---------------- scan (3 stages) -> rowptr, cursor ----------------
__global__ void k_scan1() {
    __shared__ int sh[1024];
    int i = blockIdx.x * 1024 + threadIdx.x;
    int v = (i < N_NODES) ? g_count[i] : 0;
    sh[threadIdx.x] = v;
    __syncthreads();
    for (int o = 1; o < 1024; o <<= 1) {
        int t = (threadIdx.x >= o) ? sh[threadIdx.x - o] : 0;
        __syncthreads();
        sh[threadIdx.x] += t;
        __syncthreads();
    }
    if (i < N_NODES) g_rowptr[i] = sh[threadIdx.x] - v;  // exclusive
    if (threadIdx.x == 1023) g_bsums[blockIdx.x] = sh[1023];
}

__global__ void k_scan2(int nb) {
    if (threadIdx.x == 0 && blockIdx.x == 0) {
        int acc = 0;
        for (int b = 0; b < nb; b++) {
            int t = g_bsums[b];
            g_bsums[b] = acc;
            acc += t;
        }
    }
}

__global__ void k_scan3() {
    int i = blockIdx.x * blockDim.x + threadIdx.x;
    if (i >= N_NODES) return;
    int r = g_rowptr[i] + g_bsums[i >> 10];
    g_rowptr[i] = r;
    g_cursor[i] = r;
}

// ---------------- scatter edge ids into CSR buckets ----------------
__global__ void k_scatter() {
    int e = blockIdx.x * blockDim.x + threadIdx.x;
    if (e >= N_EDGES) return;
    int p = atomicAdd(&g_cursor[g_dst[e]], 1);
    g_csr[p] = e;
}

// ---------------- aggregation + layernorm + elu + residual ----------------
#define AGG_CH 64
__global__ __launch_bounds__(256) void k_agg(const float* __restrict__ x,
                                             const float* __restrict__ ln_w,
                                             const float* __restrict__ ln_b,
                                             float* __restrict__ out) {
    int n = blockIdx.x;
    int c = threadIdx.x;       // channel 0..255
    int h = c >> 5;            // head

    __shared__ int   s_eidx[AGG_CH];
    __shared__ int   s_srcc[AGG_CH];
    __shared__ float s_w[AGG_CH][HEADS];
    __shared__ float red[8];

    int start = g_rowptr[n];
    int deg   = g_count[n];
    float invd = 1.0f / (g_denom[n * HEADS + h] + SOFTMAX_EPS);

    float acc = 0.0f;
    for (int base = 0; base < deg; base += AGG_CH) {
        int m = deg - base;
        if (m > AGG_CH) m = AGG_CH;
        __syncthreads();
        if (c < m) {
            int e = g_csr[start + base + c];
            s_eidx[c] = e;
            s_srcc[c] = g_src[e];
        }
        __syncthreads();
        for (int t = c; t < m * HEADS; t += 256)
            s_w[t >> 3][t & 7] = g_ex[(size_t)s_eidx[t >> 3] * HEADS + (t & 7)];
        __syncthreads();
#pragma unroll 4
        for (int j = 0; j < m; j++)
            acc += g_xp[(size_t)s_srcc[j] * OUT_CH + c] * s_w[j][h];
    }
    acc *= invd;

    // ---- block reduce: mean ----
    float v = acc;
#pragma unroll
    for (int o = 16; o; o >>= 1) v += __shfl_down_sync(0xffffffffu, v, o);
    __syncthreads();
    if ((c & 31) == 0) red[c >> 5] = v;
    __syncthreads();
    if (c < 8) {
        float t = red[c];
#pragma unroll
        for (int o = 4; o; o >>= 1) t += __shfl_down_sync(0xffu, t, o);
        if (c == 0) red[0] = t;
    }
    __syncthreads();
    float mu = red[0] * (1.0f / OUT_CH);
    __syncthreads();

    // ---- block reduce: variance ----
    float d0 = acc - mu;
    v = d0 * d0;
#pragma unroll
    for (int o = 16; o; o >>= 1) v += __shfl_down_sync(0xffffffffu, v, o);
    if ((c & 31) == 0) red[c >> 5] = v;
    __syncthreads();
    if (c < 8) {
        float t = red[c];
#pragma unroll
        for (int o = 4; o; o >>= 1) t += __shfl_down_sync(0xffu, t, o);
        if (c == 0) red[0] = t;
    }
    __syncthreads();
    float var = red[0] * (1.0f / OUT_CH);

    float val = d0 * rsqrtf(var + LN_EPS) * ln_w[c] + ln_b[c];
    val = (val > 0.0f) ? val : expm1f(val);
    out[(size_t)n * OUT_CH + c] = val + x[(size_t)n * OUT_CH + c];
}

// ---------------- launch ----------------
extern "C" void kernel_launch(void* const* d_in, const int* in_sizes, int n_in,
                              void* d_out, int out_size) {
    const float* x    = (const float*)d_in[0];
    const void*  ei   = d_in[1];
    const float* linw = (const float*)d_in[2];
    const float* att  = (const float*)d_in[3];
    const float* lnw  = (const float*)d_in[4];
    const float* lnb  = (const float*)d_in[5];
    float*       out  = (float*)d_out;

    (void)in_sizes; (void)n_in; (void)out_size;

    k_detect<<<1, 32>>>((const int*)ei);
    k_init<<<(N_NODES * HEADS + 255) / 256, 256>>>();
    k_prep<<<(N_EDGES + 255) / 256, 256>>>(ei);

    dim3 ggrid(OUT_CH / GBN, (N_NODES + GBM - 1) / GBM);
    k_gemm_tc<<<ggrid, 256>>>(x, linw);

    k_att<<<N_NODES, 256>>>(att);
    k_softmax<<<(N_EDGES + 255) / 256, 256>>>();

    int nscan = (N_NODES + 1023) / 1024;   // 49
    k_scan1<<<nscan, 1024>>>();
    k_scan2<<<1, 32>>>(nscan);
    k_scan3<<<(N_NODES + 255) / 256, 256>>>();

    k_scatter<<<(N_EDGES + 255) / 256, 256>>>();

    k_agg<<<N_NODES, 256>>>(x, lnw, lnb, out);
}